// round 7
// baseline (speedup 1.0000x reference)
#include <cuda_runtime.h>
#include <cstddef>

#define NEGF (-1e20f)

constexpr int NA   = 512;          // rows i = 1..512
constexpr int NBC  = 1024;         // cols j = 1..1024
constexpr int TPC  = 8;            // cols per thread
constexpr int NT   = 128;          // threads (4 warps)
constexpr int WIN  = 16;           // steps per window
constexpr int NWINS = 40;          // 640 steps >= 639 needed
constexpr int E_NEG = -(1 << 28);  // exponent of "NEG" cells (mantissa 0)

constexpr size_t ARR = (size_t)WIN * NT;             // 2048 float4 per array
constexpr size_t SMEM_B = 4 * ARR * 16 + 64;         // F0,F1,O0,O1 + bnd

// 2^d as float: exact for d in [-126,127]; 0 for very negative d.
__device__ __forceinline__ float p2(int d) {
    int k = d + 127;
    k = max(k, 0);
    return __int_as_float(k << 23);
}

__global__ void __launch_bounds__(NT, 1)
dtw_band_kernel(const float* __restrict__ W, float* __restrict__ out) {
    extern __shared__ unsigned char sm[];
    float4* F0 = (float4*)sm;            // exp(W), cols 8t..8t+3
    float4* F1 = F0 + ARR;               // exp(W), cols 8t+4..8t+7
    float4* O0 = F1 + ARR;               // mu, cols 8t..8t+3
    float4* O1 = O0 + ARR;               // mu, cols 8t+4..8t+7
    unsigned long long* bnd = (unsigned long long*)(O1 + ARR);  // [2][4]

    const int b = blockIdx.x, t = threadIdx.x, lane = t & 31, wd = t >> 5;
    const float* Wb = W + (size_t)b * NA * NBC;
    float* Ob = out + (size_t)b * (NA + 1) * (NBC + 1);

    // ---- edge outputs ----
    for (int k = t; k <= NBC; k += NT) Ob[k] = (k == 0) ? 0.0f : NEGF;
    for (int r = t + 1; r <= NA; r += NT) Ob[(size_t)r * (NBC + 1)] = NEGF;

    float tm[TPC]; int te[TPC];
    #pragma unroll
    for (int k = 0; k < TPC; ++k) { tm[k] = 0.0f; te[k] = E_NEG; }
    float pm = 0.0f; int pe = E_NEG;

    __syncthreads();

    for (int win = 0; win < NWINS; ++win) {
        const int S = WIN * win;              // window covers steps S+1..S+16

        // ---- fill exp(W) for this window (coalesced row segments) ----
        // consume rows r = s-t-1, s in window -> r in [S-127, S+15], 143 rows
        for (int m = wd; m < 143; m += 4) {
            int r = S - 127 + m;
            if ((unsigned)r < (unsigned)NA) {
                int tlo = max(S - r, 0), thi = min(S + 15 - r, 127);
                int tt = tlo + (lane >> 1), h = lane & 1;
                if (tt <= thi) {
                    float4 v = *(const float4*)(Wb + (size_t)r * NBC + TPC * tt + 4 * h);
                    float4 f;
                    f.x = __expf(v.x); f.y = __expf(v.y);
                    f.z = __expf(v.z); f.w = __expf(v.w);
                    int sg = (r + tt + 1) & (WIN - 1);
                    (h ? F1 : F0)[sg * NT + tt] = f;
                }
            }
        }
        // ---- flush previous window's outputs (coalesced row segments) ----
        if (win > 0) {
            const int Sp = S - WIN;          // rows i = s-t -> [Sp-126, Sp+16]
            for (int m = wd; m < 143; m += 4) {
                int r = Sp - 126 + m;
                if (r >= 1 && r <= NA) {
                    int tlo = max(Sp + 1 - r, 0), thi = min(Sp + 16 - r, 127);
                    int tt = tlo + (lane >> 1), h = lane & 1;
                    if (tt <= thi) {
                        int sg = (r + tt) & (WIN - 1);
                        float4 v = (h ? O1 : O0)[sg * NT + tt];
                        float* g = Ob + (size_t)r * (NBC + 1) + TPC * tt + 4 * h + 1;
                        g[0] = v.x; g[1] = v.y; g[2] = v.z; g[3] = v.w;
                    }
                }
            }
        }
        __syncthreads();

        // ---- 16 lockstep wavefront steps ----
        #pragma unroll 1
        for (int q = 1; q <= WIN; ++q) {
            const int s = S + q;
            const int i = s - t;
            const bool act = (unsigned)(i - 1) < (unsigned)NA;

            float lvm = __shfl_up_sync(0xFFFFFFFFu, tm[TPC - 1], 1);
            int   lve = __shfl_up_sync(0xFFFFFFFFu, te[TPC - 1], 1);
            if (lane == 0 && wd > 0) {
                unsigned long long pk = bnd[(s & 1) * 4 + wd - 1];
                lvm = __uint_as_float((unsigned)pk);
                lve = (int)(pk >> 32);
            }
            if (t == 0) { lvm = 0.0f; lve = E_NEG; }

            float dm = pm; int de = pe;
            if (i == 1) { dm = (t == 0) ? 1.0f : 0.0f; de = (t == 0) ? 0 : E_NEG; }
            pm = lvm; pe = lve;

            if (act) {
                const int sg = s & (WIN - 1);
                float4 fA = F0[sg * NT + t];
                float4 fB = F1[sg * NT + t];
                float fv[TPC] = {fA.x, fA.y, fA.z, fA.w, fB.x, fB.y, fB.z, fB.w};

                int e_base = max(lve, max(te[0], de));
                float leftm = lvm * p2(lve - e_base);
                float om[TPC];
                float prev_m = dm; int prev_e = de;

                #pragma unroll
                for (int k = 0; k < TPC; ++k) {
                    float pt = p2(te[k] - e_base);
                    float pd = p2(prev_e - e_base);
                    float sacc = fmaf(tm[k], pt, fmaf(prev_m, pd, leftm));
                    leftm = sacc * fv[k];
                    prev_m = tm[k]; prev_e = te[k];
                    int bits = __float_as_int(leftm);
                    int ee = (bits >> 23) - 127;
                    tm[k] = __int_as_float((bits & 0x007FFFFF) | 0x3F800000);
                    te[k] = e_base + ee;
                    om[k] = ((float)te[k] + __log2f(tm[k])) * 0.69314718056f;
                }
                O0[sg * NT + t] = make_float4(om[0], om[1], om[2], om[3]);
                O1[sg * NT + t] = make_float4(om[4], om[5], om[6], om[7]);

                if (lane == 31)
                    bnd[((s + 1) & 1) * 4 + wd] =
                        ((unsigned long long)(unsigned)te[TPC - 1] << 32) |
                        (unsigned long long)__float_as_uint(tm[TPC - 1]);
            }
            __syncthreads();
        }
    }

    // ---- flush the final window ----
    {
        const int Sp = WIN * (NWINS - 1);
        for (int m = wd; m < 143; m += 4) {
            int r = Sp - 126 + m;
            if (r >= 1 && r <= NA) {
                int tlo = max(Sp + 1 - r, 0), thi = min(Sp + 16 - r, 127);
                int tt = tlo + (lane >> 1), h = lane & 1;
                if (tt <= thi) {
                    int sg = (r + tt) & (WIN - 1);
                    float4 v = (h ? O1 : O0)[sg * NT + tt];
                    float* g = Ob + (size_t)r * (NBC + 1) + TPC * tt + 4 * h + 1;
                    g[0] = v.x; g[1] = v.y; g[2] = v.z; g[3] = v.w;
                }
            }
        }
    }
}

extern "C" void kernel_launch(void* const* d_in, const int* in_sizes, int n_in,
                              void* d_out, int out_size) {
    const float* W = (const float*)d_in[0];
    float* out = (float*)d_out;
    cudaFuncSetAttribute(dtw_band_kernel,
                         cudaFuncAttributeMaxDynamicSharedMemorySize,
                         (int)SMEM_B);
    dtw_band_kernel<<<32, NT, SMEM_B>>>(W, out);
}

// round 8
// speedup vs baseline: 2.8057x; 2.8057x over previous
#include <cuda_runtime.h>
#include <cstddef>
#include <cstdint>

#define NEGF (-1e20f)

constexpr int NA   = 512;
constexpr int NBC  = 1024;
constexpr int TPC  = 8;
constexpr int NT   = 128;          // 4 warps
constexpr int WIN  = 16;
constexpr int NWINS = 40;          // 640 steps >= 639
constexpr int E_NEG = -(1 << 28);

constexpr int F_F4 = 2 * WIN * NT * 2;   // double-buffered raw-W band, float4 units
constexpr int O_F4 = WIN * NT * 2;       // output band
constexpr size_t SMEM_B = (size_t)(F_F4 + O_F4) * 16 + 64;

__device__ __forceinline__ float p2(int d) {
    int k = max(d + 127, 0);
    return __int_as_float(k << 23);
}
__device__ __forceinline__ void cpa16(uint32_t dst, const void* src) {
    asm volatile("cp.async.cg.shared.global [%0], [%1], 16;" :: "r"(dst), "l"(src));
}

__global__ void __launch_bounds__(NT, 1)
dtw_cpasync_kernel(const float* __restrict__ W, float* __restrict__ out) {
    extern __shared__ unsigned char sm[];
    float4* F = (float4*)sm;                                   // [2][WIN][NT][2]
    float4* O = F + F_F4;                                      // [WIN][NT][2]
    unsigned long long* bnd = (unsigned long long*)(O + O_F4); // [2][4]

    const int b = blockIdx.x, t = threadIdx.x, lane = t & 31, wd = t >> 5;
    const float* Wb = W + (size_t)b * NA * NBC;
    float* Ob = out + (size_t)b * (NA + 1) * (NBC + 1);
    const uint32_t Fs = (uint32_t)__cvta_generic_to_shared(F);

    // ---- edge outputs ----
    for (int k = t; k <= NBC; k += NT) Ob[k] = (k == 0) ? 0.0f : NEGF;
    for (int r = t + 1; r <= NA; r += NT) Ob[(size_t)r * (NBC + 1)] = NEGF;

    float tm[TPC]; int te[TPC];
    #pragma unroll
    for (int k = 0; k < TPC; ++k) { tm[k] = 0.0f; te[k] = E_NEG; }
    float pm = 0.0f; int pe = E_NEG;

    // issue a window's raw-W fill via cp.async (coalesced 512B per row)
    auto issue_fill = [&](int w) {
        if (w >= NWINS) return;
        const int S = WIN * w;
        const int p = w & 1;
        for (int m = wd; m < 143; m += 4) {
            int r = S - 127 + m;
            if ((unsigned)r < (unsigned)NA) {
                int tlo = max(S - r, 0), thi = min(S + 15 - r, 127);
                int tt = tlo + (lane >> 1), h = lane & 1;
                if (tt <= thi) {
                    int sg = (r + tt + 1) & (WIN - 1);
                    uint32_t dst = Fs + (uint32_t)((((p * WIN + sg) * NT + tt) * 2 + h) * 16);
                    cpa16(dst, Wb + (size_t)r * NBC + 8 * tt + 4 * h);
                }
            }
        }
        asm volatile("cp.async.commit_group;" ::: "memory");
    };
    // flush a computed window's outputs (coalesced-ish, fire-and-forget STG.32)
    auto flush_win = [&](int w) {
        const int Sp = WIN * w;
        for (int m = wd; m < 143; m += 4) {
            int i = Sp - 126 + m;
            if (i >= 1 && i <= NA) {
                int tlo = max(Sp + 1 - i, 0), thi = min(Sp + WIN - i, 127);
                int tt = tlo + (lane >> 1), h = lane & 1;
                if (tt <= thi) {
                    int sg = (i + tt) & (WIN - 1);
                    float4 v = O[(sg * NT + tt) * 2 + h];
                    float* g = Ob + (size_t)i * (NBC + 1) + 8 * tt + 4 * h + 1;
                    g[0] = v.x; g[1] = v.y; g[2] = v.z; g[3] = v.w;
                }
            }
        }
    };

    issue_fill(0);
    __syncthreads();

    for (int win = 0; win < NWINS; ++win) {
        const int S = WIN * win;
        asm volatile("cp.async.wait_group 0;" ::: "memory");  // fill(win) landed
        __syncthreads();                                      // visible to all warps
        issue_fill(win + 1);                                  // overlaps this window
        if (win > 0) flush_win(win - 1);
        __syncthreads();                                      // O band reusable

        #pragma unroll 1
        for (int q = 1; q <= WIN; ++q) {
            const int s = S + q;
            const int i = s - t;
            const bool act = (unsigned)(i - 1) < (unsigned)NA;

            float lvm = __shfl_up_sync(0xFFFFFFFFu, tm[TPC - 1], 1);
            int   lve = __shfl_up_sync(0xFFFFFFFFu, te[TPC - 1], 1);
            if (lane == 0 && wd > 0) {
                unsigned long long pk = bnd[(s & 1) * 4 + wd - 1];
                lvm = __uint_as_float((unsigned)pk);
                lve = (int)(pk >> 32);
            }
            if (t == 0) { lvm = 0.0f; lve = E_NEG; }

            float dm = pm; int de = pe;
            if (i == 1) { dm = (t == 0) ? 1.0f : 0.0f; de = (t == 0) ? 0 : E_NEG; }
            pm = lvm; pe = lve;

            if (act) {
                const int sg = s & (WIN - 1);
                const int base = ((win & 1) * WIN + sg) * NT + t;
                float4 fA = F[base * 2];
                float4 fB = F[base * 2 + 1];
                float wv[TPC] = {fA.x, fA.y, fA.z, fA.w, fB.x, fB.y, fB.z, fB.w};

                int e_base = max(lve, max(te[0], de));
                float leftm = lvm * p2(lve - e_base);
                float om[TPC];
                float prev_m = dm; int prev_e = de;

                #pragma unroll
                for (int k = 0; k < TPC; ++k) {
                    float f  = __expf(wv[k]);
                    float pt = p2(te[k] - e_base);
                    float pd = p2(prev_e - e_base);
                    float sacc = fmaf(tm[k], pt, fmaf(prev_m, pd, leftm));
                    leftm = sacc * f;
                    prev_m = tm[k]; prev_e = te[k];
                    int bits = __float_as_int(leftm);
                    int ee = (bits >> 23) - 127;
                    tm[k] = __int_as_float((bits & 0x007FFFFF) | 0x3F800000);
                    te[k] = e_base + ee;
                    om[k] = ((float)te[k] + __log2f(tm[k])) * 0.69314718056f;
                }
                int ob = (sg * NT + t) * 2;
                O[ob]     = make_float4(om[0], om[1], om[2], om[3]);
                O[ob + 1] = make_float4(om[4], om[5], om[6], om[7]);

                if (lane == 31)
                    bnd[((s + 1) & 1) * 4 + wd] =
                        ((unsigned long long)(unsigned)te[TPC - 1] << 32) |
                        (unsigned long long)__float_as_uint(tm[TPC - 1]);
            }
            __syncthreads();
        }
    }

    flush_win(NWINS - 1);
}

extern "C" void kernel_launch(void* const* d_in, const int* in_sizes, int n_in,
                              void* d_out, int out_size) {
    const float* W = (const float*)d_in[0];
    float* out = (float*)d_out;
    cudaFuncSetAttribute(dtw_cpasync_kernel,
                         cudaFuncAttributeMaxDynamicSharedMemorySize,
                         (int)SMEM_B);
    dtw_cpasync_kernel<<<32, NT, SMEM_B>>>(W, out);
}